// round 15
// baseline (speedup 1.0000x reference)
#include <cuda_runtime.h>
#include <cuda_fp16.h>
#include <cstdint>
#include <cstddef>

#define N_NODES 8192
#define NFEAT   512
#define NHID    256
#define MAXD    256   // max neighbors kept per row (mean ~83, P(>256) ~ 0)
#define HALF_N  (N_NODES / 2)

// ---------------- scratch (device globals: no allocation allowed) -----------
__device__ int    g_cols[N_NODES * MAXD];    // ELL column indices (8 MB)
__device__ int    g_deg [N_NODES];
__device__ __half g_Whh [N_NODES * NHID];    // layer-1 Wh fp16 (4 MB)
__device__ __half g_Whh2[N_NODES * NHID];    // layer-2 Wh fp16 (4 MB)
__device__ __half g_Ahi [N_NODES * NHID];    // layer-2 A operand, fp16 hi (4 MB)
__device__ __half g_Alo [N_NODES * NHID];    // layer-2 A operand, fp16 lo (4 MB)
__device__ __half g_W1hiT[NHID * 512];       // W1^T [n][k] fp16 hi
__device__ __half g_W1loT[NHID * 512];
__device__ __half g_W2hiT[NHID * 512];       // W2^T [n][k] (first 256 k used)
__device__ __half g_W2loT[NHID * 512];
__device__ float  g_fs [N_NODES], g_fd [N_NODES];   // layer-1 f-vectors
__device__ float  g_fs2[N_NODES], g_fd2[N_NODES];   // layer-2 f-vectors

// ---------------- packed f32x2 helpers (Blackwell) --------------------------
__device__ __forceinline__ unsigned long long pack_f32x2(float lo, float hi) {
    unsigned long long r;
    asm("mov.b64 %0, {%1, %2};" : "=l"(r) : "f"(lo), "f"(hi));
    return r;
}
__device__ __forceinline__ void unpack_f32x2(float& lo, float& hi, unsigned long long v) {
    asm("mov.b64 {%0, %1}, %2;" : "=f"(lo), "=f"(hi) : "l"(v));
}
#define FMA_F32X2(acc, a, b) \
    asm("fma.rn.f32x2 %0, %1, %2, %0;" : "+l"(acc) : "l"(a), "l"(b))

// ---------------- 0) weight transpose+split, W1 and W2 in ONE launch --------
__global__ __launch_bounds__(256) void conv_weights(const float* __restrict__ W1,
                                                    const float* __restrict__ W2) {
    int b = blockIdx.x;
    const float* W;
    __half *hiT, *loT;
    int i;
    if (b < 512) {
        W = W1; i = b * 256 + threadIdx.x;
        hiT = g_W1hiT; loT = g_W1loT;
    } else {
        W = W2; i = (b - 512) * 256 + threadIdx.x;
        hiT = g_W2hiT; loT = g_W2loT;
    }
    int k = i >> 8, n = i & 255;
    float v = W[i];
    __half h = __float2half_rn(v);
    hiT[n * 512 + k] = h;
    loT[n * 512 + k] = __float2half_rn(v - __half2float(h));
}

// ---------------- 1) adjacency -> ELL: maskless compaction, streaming loads -
__global__ __launch_bounds__(256) void build_ell(const float* __restrict__ adj, int rowOff) {
    const int w    = threadIdx.x >> 5;
    const int lane = threadIdx.x & 31;
    const int row  = rowOff + blockIdx.x * 8 + w;

    const float4* arow = (const float4*)(adj + (size_t)row * N_NODES);  // 2048 float4
    int* crow = g_cols + row * MAXD;

    int cnt = 0;
    #pragma unroll 1
    for (int ch = 0; ch < 8; ch++) {
        const float4* p = arow + ch * 256;
        float4 v[8];
        #pragma unroll
        for (int i = 0; i < 8; i++) v[i] = __ldcs(p + i * 32 + lane);  // streaming

        unsigned mask = 0;
        #pragma unroll
        for (int i = 0; i < 8; i++) {
            mask |= (v[i].x > 0.f ? 1u : 0u) << (i * 4 + 0);
            mask |= (v[i].y > 0.f ? 1u : 0u) << (i * 4 + 1);
            mask |= (v[i].z > 0.f ? 1u : 0u) << (i * 4 + 2);
            mask |= (v[i].w > 0.f ? 1u : 0u) << (i * 4 + 3);
        }
        int c = __popc(mask);
        int incl = c;
        #pragma unroll
        for (int o = 1; o < 32; o <<= 1) {
            int n = __shfl_up_sync(0xffffffffu, incl, o);
            if (lane >= o) incl += n;
        }
        int pos = cnt + incl - c;                 // exclusive prefix
        const int cb = ch * 1024 + lane * 4;      // bit b -> col cb + (b>>2)*128 + (b&3)
        while (mask) {
            int b = __ffs(mask) - 1;
            mask &= mask - 1;
            if (pos < MAXD) crow[pos] = cb + ((b >> 2) << 7) + (b & 3);
            pos++;
        }
        cnt += __shfl_sync(0xffffffffu, incl, 31);  // chunk total
    }
    if (lane == 0) g_deg[row] = (cnt < MAXD) ? cnt : MAXD;
}

// ---------------- 2) tensor-core GEMM (split-fp16, fp32-accurate) -----------
// Templated on A source: F32A=true reads fp32 A and splits to hi/lo in
// registers (layer 1); F32A=false reads pre-split Ahi/Alo (layer 2).
// Compile-time branch -> no dead-path registers. launch_bounds(256,3) caps
// regs for 3 CTAs/SM.
__device__ __forceinline__ void mma16816(float* c, const unsigned* a, const unsigned* b) {
    asm volatile(
        "mma.sync.aligned.m16n8k16.row.col.f32.f16.f16.f32 "
        "{%0,%1,%2,%3}, {%4,%5,%6,%7}, {%8,%9}, {%0,%1,%2,%3};\n"
        : "+f"(c[0]), "+f"(c[1]), "+f"(c[2]), "+f"(c[3])
        : "r"(a[0]), "r"(a[1]), "r"(a[2]), "r"(a[3]), "r"(b[0]), "r"(b[1]));
}

#define AS_STRIDE 24   // 16 halves + 8 pad: (12g+tg) mod 32 all-distinct banks

template<bool F32A>
__global__ __launch_bounds__(256, 3) void gemm_tc(const float* __restrict__ Af,
                                                  const __half* __restrict__ Ahi,
                                                  const __half* __restrict__ Alo,
                                                  const __half* __restrict__ BhiT,
                                                  const __half* __restrict__ BloT,
                                                  int K, __half* __restrict__ C, int yOff) {
    __shared__ __half sAhi[2][64 * AS_STRIDE],  sAlo[2][64 * AS_STRIDE];
    __shared__ __half sBhi[2][128 * AS_STRIDE], sBlo[2][128 * AS_STRIDE];

    const int tid = threadIdx.x;
    const int wid = tid >> 5, lane = tid & 31;
    const int g = lane >> 2, tg = lane & 3;
    const int warpM = wid >> 2, warpN = wid & 3;    // 2 x 4 warps
    const int rowBase = (blockIdx.y + yOff) * 64;
    const int nBase   = blockIdx.x * 128;

    const int la_r  = tid >> 2,          la_s  = tid & 3;
    const int lb_r0 = (tid * 2)     >> 2, lb_s0 = (tid * 2)     & 3;
    const int lb_r1 = (tid * 2 + 1) >> 2, lb_s1 = (tid * 2 + 1) & 3;

    const float*  Afp = F32A ? Af + (size_t)(rowBase + la_r) * K + la_s * 4 : nullptr;
    const __half* Ah  = Ahi + (size_t)(rowBase + la_r) * K + la_s * 4;
    const __half* Al  = Alo + (size_t)(rowBase + la_r) * K + la_s * 4;
    const __half* Bh0 = BhiT + (size_t)(nBase + lb_r0) * 512 + lb_s0 * 4;
    const __half* Bh1 = BhiT + (size_t)(nBase + lb_r1) * 512 + lb_s1 * 4;
    const __half* Bl0 = BloT + (size_t)(nBase + lb_r0) * 512 + lb_s0 * 4;
    const __half* Bl1 = BloT + (size_t)(nBase + lb_r1) * 512 + lb_s1 * 4;

    uint2 rAh, rAl, rBh0, rBh1, rBl0, rBl1;
    auto ldg = [&](int k0) {
        if (F32A) {
            float4 va = *(const float4*)(Afp + k0);
            __half hx = __float2half_rn(va.x), hy = __float2half_rn(va.y);
            __half hz = __float2half_rn(va.z), hw = __float2half_rn(va.w);
            __half2 h01 = __halves2half2(hx, hy), h23 = __halves2half2(hz, hw);
            __half2 l01 = __halves2half2(__float2half_rn(va.x - __half2float(hx)),
                                         __float2half_rn(va.y - __half2float(hy)));
            __half2 l23 = __halves2half2(__float2half_rn(va.z - __half2float(hz)),
                                         __float2half_rn(va.w - __half2float(hw)));
            rAh.x = *(unsigned*)&h01; rAh.y = *(unsigned*)&h23;
            rAl.x = *(unsigned*)&l01; rAl.y = *(unsigned*)&l23;
        } else {
            rAh = *(const uint2*)(Ah + k0);
            rAl = *(const uint2*)(Al + k0);
        }
        rBh0 = *(const uint2*)(Bh0 + k0);
        rBh1 = *(const uint2*)(Bh1 + k0);
        rBl0 = *(const uint2*)(Bl0 + k0);
        rBl1 = *(const uint2*)(Bl1 + k0);
    };
    auto sts = [&](int buf) {
        *(uint2*)&sAhi[buf][la_r * AS_STRIDE + la_s * 4]    = rAh;
        *(uint2*)&sAlo[buf][la_r * AS_STRIDE + la_s * 4]    = rAl;
        *(uint2*)&sBhi[buf][lb_r0 * AS_STRIDE + lb_s0 * 4]  = rBh0;
        *(uint2*)&sBhi[buf][lb_r1 * AS_STRIDE + lb_s1 * 4]  = rBh1;
        *(uint2*)&sBlo[buf][lb_r0 * AS_STRIDE + lb_s0 * 4]  = rBl0;
        *(uint2*)&sBlo[buf][lb_r1 * AS_STRIDE + lb_s1 * 4]  = rBl1;
    };

    float acc[2][4][4] = {};

    ldg(0); sts(0); __syncthreads();
    const int T = K / 16;
    for (int t = 0; t < T; t++) {
        const int buf = t & 1;
        if (t + 1 < T) ldg((t + 1) * 16);

        unsigned ahi[2][4], alo[2][4], bhi[4][2], blo[4][2];
        #pragma unroll
        for (int mt = 0; mt < 2; mt++) {
            int r0 = warpM * 32 + mt * 16 + g;
            ahi[mt][0] = *(const unsigned*)&sAhi[buf][(r0    ) * AS_STRIDE + tg * 2];
            ahi[mt][1] = *(const unsigned*)&sAhi[buf][(r0 + 8) * AS_STRIDE + tg * 2];
            ahi[mt][2] = *(const unsigned*)&sAhi[buf][(r0    ) * AS_STRIDE + tg * 2 + 8];
            ahi[mt][3] = *(const unsigned*)&sAhi[buf][(r0 + 8) * AS_STRIDE + tg * 2 + 8];
            alo[mt][0] = *(const unsigned*)&sAlo[buf][(r0    ) * AS_STRIDE + tg * 2];
            alo[mt][1] = *(const unsigned*)&sAlo[buf][(r0 + 8) * AS_STRIDE + tg * 2];
            alo[mt][2] = *(const unsigned*)&sAlo[buf][(r0    ) * AS_STRIDE + tg * 2 + 8];
            alo[mt][3] = *(const unsigned*)&sAlo[buf][(r0 + 8) * AS_STRIDE + tg * 2 + 8];
        }
        #pragma unroll
        for (int nt = 0; nt < 4; nt++) {
            int n0 = warpN * 32 + nt * 8 + g;
            bhi[nt][0] = *(const unsigned*)&sBhi[buf][n0 * AS_STRIDE + tg * 2];
            bhi[nt][1] = *(const unsigned*)&sBhi[buf][n0 * AS_STRIDE + tg * 2 + 8];
            blo[nt][0] = *(const unsigned*)&sBlo[buf][n0 * AS_STRIDE + tg * 2];
            blo[nt][1] = *(const unsigned*)&sBlo[buf][n0 * AS_STRIDE + tg * 2 + 8];
        }
        #pragma unroll
        for (int mt = 0; mt < 2; mt++)
            #pragma unroll
            for (int nt = 0; nt < 4; nt++) {
                mma16816(acc[mt][nt], ahi[mt], bhi[nt]);
                mma16816(acc[mt][nt], ahi[mt], blo[nt]);
                mma16816(acc[mt][nt], alo[mt], bhi[nt]);
            }
        if (t + 1 < T) sts(buf ^ 1);
        __syncthreads();
    }

    #pragma unroll
    for (int mt = 0; mt < 2; mt++) {
        int r0 = rowBase + warpM * 32 + mt * 16 + g;
        #pragma unroll
        for (int nt = 0; nt < 4; nt++) {
            int c = nBase + warpN * 32 + nt * 8 + tg * 2;
            __half2 h0 = __floats2half2_rn(acc[mt][nt][0], acc[mt][nt][1]);
            __half2 h1 = __floats2half2_rn(acc[mt][nt][2], acc[mt][nt][3]);
            *(__half2*)&C[(size_t)r0 * NHID + c]       = h0;
            *(__half2*)&C[(size_t)(r0 + 8) * NHID + c] = h1;
        }
    }
}

// ---------------- 3) f_src / f_dst: warp-per-row dot(Wh[row], a_half) -------
__global__ __launch_bounds__(256) void fvec_kernel(const __half* __restrict__ Wh,
                                                   const float* __restrict__ a,
                                                   float* __restrict__ fs,
                                                   float* __restrict__ fd, int rowOff) {
    const int w    = threadIdx.x >> 5;
    const int lane = threadIdx.x & 31;
    const int row  = rowOff + blockIdx.x * 8 + w;

    uint4 wv = *(const uint4*)&Wh[(size_t)row * NHID + lane * 8];
    float2 f0 = __half22float2(*(__half2*)&wv.x);
    float2 f1 = __half22float2(*(__half2*)&wv.y);
    float2 f2 = __half22float2(*(__half2*)&wv.z);
    float2 f3 = __half22float2(*(__half2*)&wv.w);

    float4 a0 = *(const float4*)(a + lane * 8);
    float4 a1 = *(const float4*)(a + lane * 8 + 4);
    float4 b0 = *(const float4*)(a + NHID + lane * 8);
    float4 b1 = *(const float4*)(a + NHID + lane * 8 + 4);

    float s1 = f0.x * a0.x + f0.y * a0.y + f1.x * a0.z + f1.y * a0.w
             + f2.x * a1.x + f2.y * a1.y + f3.x * a1.z + f3.y * a1.w;
    float s2 = f0.x * b0.x + f0.y * b0.y + f1.x * b0.z + f1.y * b0.w
             + f2.x * b1.x + f2.y * b1.y + f3.x * b1.z + f3.y * b1.w;
    #pragma unroll
    for (int o = 16; o > 0; o >>= 1) {
        s1 += __shfl_xor_sync(0xffffffffu, s1, o);
        s2 += __shfl_xor_sync(0xffffffffu, s2, o);
    }
    if (lane == 0) { fs[row] = s1; fd[row] = s2; }
}

// ---------------- 4) attn: warp-per-row softmax + SpMM (f32x2) + double ELU -
__global__ __launch_bounds__(256) void attn_kernel(const __half* __restrict__ Wh,
                                                   const float* __restrict__ fs,
                                                   const float* __restrict__ fd,
                                                   float* __restrict__ out,
                                                   int half_out, int rowOff) {
    const int w    = threadIdx.x >> 5;
    const int lane = threadIdx.x & 31;
    const int row  = rowOff + blockIdx.x * 8 + w;

    __shared__ float2 sp[8][MAXD];   // {p_j, byte-offset of Wh row as int bits}

    const int d = g_deg[row];
    const int* crow = g_cols + row * MAXD;
    const float fsr = fs[row];

    float e[8];
    int   c[8];
    #pragma unroll
    for (int i = 0; i < 8; i++) {
        int j = lane + 32 * i;
        if (j < d) {
            c[i] = crow[j];
            float v = fsr + fd[c[i]];
            e[i] = (v > 0.f) ? v : 0.2f * v;    // LeakyReLU(0.2)
        } else {
            e[i] = -3.0e38f;
        }
    }
    float m = e[0];
    #pragma unroll
    for (int i = 1; i < 8; i++) m = fmaxf(m, e[i]);
    #pragma unroll
    for (int o = 16; o > 0; o >>= 1) m = fmaxf(m, __shfl_xor_sync(0xffffffffu, m, o));

    float s = 0.f;
    #pragma unroll
    for (int i = 0; i < 8; i++) {
        int j = lane + 32 * i;
        if (j < d) {
            float pe = expf(e[i] - m);
            s += pe;
            sp[w][j] = make_float2(pe, __int_as_float(c[i] << 9));  // row stride 512 B
        }
    }
    #pragma unroll
    for (int o = 16; o > 0; o >>= 1) s += __shfl_xor_sync(0xffffffffu, s, o);
    const float inv = 1.f / s;
    __syncwarp();

    const char* whbase = (const char*)Wh + lane * 16;
    unsigned long long acc2[4];
    #pragma unroll
    for (int i = 0; i < 4; i++) acc2[i] = pack_f32x2(0.f, 0.f);

    #pragma unroll 8
    for (int j = 0; j < d; j++) {
        float2 po = sp[w][j];
        unsigned long long pj2 = pack_f32x2(po.x, po.x);
        uint4 wv = *(const uint4*)(whbase + __float_as_int(po.y));
        float2 f0 = __half22float2(*(__half2*)&wv.x);
        float2 f1 = __half22float2(*(__half2*)&wv.y);
        float2 f2 = __half22float2(*(__half2*)&wv.z);
        float2 f3 = __half22float2(*(__half2*)&wv.w);
        unsigned long long w0 = pack_f32x2(f0.x, f0.y);
        unsigned long long w1 = pack_f32x2(f1.x, f1.y);
        unsigned long long w2 = pack_f32x2(f2.x, f2.y);
        unsigned long long w3 = pack_f32x2(f3.x, f3.y);
        FMA_F32X2(acc2[0], pj2, w0);
        FMA_F32X2(acc2[1], pj2, w1);
        FMA_F32X2(acc2[2], pj2, w2);
        FMA_F32X2(acc2[3], pj2, w3);
    }

    float acc[8];
    unpack_f32x2(acc[0], acc[1], acc2[0]);
    unpack_f32x2(acc[2], acc[3], acc2[1]);
    unpack_f32x2(acc[4], acc[5], acc2[2]);
    unpack_f32x2(acc[6], acc[7], acc2[3]);

    float h[8];
    #pragma unroll
    for (int i = 0; i < 8; i++) {
        float v = acc[i] * inv;
        float x1 = (v > 0.f) ? v : expm1f(v);
        h[i] = (x1 > 0.f) ? x1 : expm1f(x1);
    }

    if (half_out) {
        __half hi[8], lo[8];
        #pragma unroll
        for (int i = 0; i < 8; i++) {
            hi[i] = __float2half_rn(h[i]);
            lo[i] = __float2half_rn(h[i] - __half2float(hi[i]));
        }
        *(uint4*)&g_Ahi[(size_t)row * NHID + lane * 8] = *(uint4*)hi;
        *(uint4*)&g_Alo[(size_t)row * NHID + lane * 8] = *(uint4*)lo;
    } else {
        float* o = out + (size_t)row * NHID + lane * 8;
        *(float4*)(o + 0) = make_float4(h[0], h[1], h[2], h[3]);
        *(float4*)(o + 4) = make_float4(h[4], h[5], h[6], h[7]);
    }
}

// ---------------- launch ----------------------------------------------------
extern "C" void kernel_launch(void* const* d_in, const int* in_sizes, int n_in,
                              void* d_out, int out_size) {
    const float* x   = (const float*)d_in[0];   // [8192, 512]
    const float* adj = (const float*)d_in[1];   // [8192, 8192]
    const float* W1  = (const float*)d_in[2];   // [512, 256]
    const float* a1  = (const float*)d_in[3];   // [512, 1]
    const float* W2  = (const float*)d_in[4];   // [256, 256]
    const float* a2  = (const float*)d_in[5];   // [512, 1]
    float* out = (float*)d_out;                 // [8192, 256]

    __half *Ahi, *Alo, *W1h, *W1l, *W2h, *W2l, *Whh, *Whh2;
    float *fs, *fd, *fs2, *fd2;
    cudaGetSymbolAddress((void**)&Ahi, g_Ahi);
    cudaGetSymbolAddress((void**)&Alo, g_Alo);
    cudaGetSymbolAddress((void**)&W1h, g_W1hiT);
    cudaGetSymbolAddress((void**)&W1l, g_W1loT);
    cudaGetSymbolAddress((void**)&W2h, g_W2hiT);
    cudaGetSymbolAddress((void**)&W2l, g_W2loT);
    cudaGetSymbolAddress((void**)&Whh, g_Whh);
    cudaGetSymbolAddress((void**)&Whh2, g_Whh2);
    cudaGetSymbolAddress((void**)&fs, g_fs);
    cudaGetSymbolAddress((void**)&fd, g_fd);
    cudaGetSymbolAddress((void**)&fs2, g_fs2);
    cudaGetSymbolAddress((void**)&fd2, g_fd2);

    dim3 gridFull(NHID / 128, N_NODES / 64);    // (2, 128)
    dim3 gridHalf(NHID / 128, HALF_N / 64);     // (2, 64)

    // ONE side stream (proven-clean resource profile). sB carries:
    //   build_a -> build_b -> [wait fvec1] -> attn1_b -> gemm2_b -> fvec2_b
    // while main carries conv/gemm1/fvec1 then the half-A pipeline.
    cudaStream_t sB;
    cudaEvent_t evFork, evBA, evPrep, evX;
    cudaStreamCreateWithFlags(&sB, cudaStreamNonBlocking);
    cudaEventCreateWithFlags(&evFork, cudaEventDisableTiming);
    cudaEventCreateWithFlags(&evBA, cudaEventDisableTiming);
    cudaEventCreateWithFlags(&evPrep, cudaEventDisableTiming);
    cudaEventCreateWithFlags(&evX, cudaEventDisableTiming);

    cudaEventRecord(evFork, 0);
    cudaStreamWaitEvent(sB, evFork, 0);
    build_ell<<<HALF_N / 8, 256, 0, sB>>>(adj, 0);
    cudaEventRecord(evBA, sB);
    build_ell<<<HALF_N / 8, 256, 0, sB>>>(adj, HALF_N);

    // main: weights prep + layer-1 GEMM (fp32 x, compile-time split) + fvec1
    conv_weights<<<768, 256>>>(W1, W2);
    gemm_tc<true><<<gridFull, 256>>>(x, Ahi, Alo, W1h, W1l, NFEAT, Whh, 0);
    fvec_kernel<<<N_NODES / 8, 256>>>(Whh, a1, fs, fd, 0);
    cudaEventRecord(evPrep, 0);

    // sB continues: half-B pipeline (after build_b by program order + fvec1)
    cudaStreamWaitEvent(sB, evPrep, 0);
    attn_kernel<<<HALF_N / 8, 256, 0, sB>>>(Whh, fs, fd, nullptr, 1, HALF_N);
    gemm_tc<false><<<gridHalf, 256, 0, sB>>>(nullptr, Ahi, Alo, W2h, W2l, NHID, Whh2, HALF_N / 64);
    fvec_kernel<<<HALF_N / 8, 256, 0, sB>>>(Whh2, a2, fs2, fd2, HALF_N);
    cudaEventRecord(evX, sB);

    // main: half-A pipeline (starts as soon as build_a is done)
    cudaStreamWaitEvent(0, evBA, 0);
    attn_kernel<<<HALF_N / 8, 256>>>(Whh, fs, fd, nullptr, 1, 0);
    gemm_tc<false><<<gridHalf, 256>>>(nullptr, Ahi, Alo, W2h, W2l, NHID, Whh2, 0);
    fvec_kernel<<<HALF_N / 8, 256>>>(Whh2, a2, fs2, fd2, 0);

    // join: attn2 needs full Whh2 + fs2/fd2 + full g_cols
    cudaStreamWaitEvent(0, evX, 0);
    attn_kernel<<<N_NODES / 8, 256>>>(Whh2, fs2, fd2, out, 0, 0);
}

// round 17
// speedup vs baseline: 1.0801x; 1.0801x over previous
#include <cuda_runtime.h>
#include <cuda_fp16.h>
#include <cstdint>
#include <cstddef>

#define N_NODES 8192
#define NFEAT   512
#define NHID    256
#define MAXD    256   // max neighbors kept per row (mean ~83, P(>256) ~ 0)
#define HALF_N  (N_NODES / 2)

// ---------------- scratch (device globals: no allocation allowed) -----------
__device__ int    g_cols[N_NODES * MAXD];    // ELL column indices (8 MB)
__device__ int    g_deg [N_NODES];
__device__ __half g_Whh [N_NODES * NHID];    // layer-1 Wh fp16 (4 MB)
__device__ __half g_Whh2[N_NODES * NHID];    // layer-2 Wh fp16 (4 MB)
__device__ __half g_Ahi [N_NODES * NHID];    // layer-2 A operand, fp16 hi (4 MB)
__device__ __half g_Alo [N_NODES * NHID];    // layer-2 A operand, fp16 lo (4 MB)
__device__ __half g_W1hiT[NHID * 512];       // W1^T [n][k] fp16 hi
__device__ __half g_W1loT[NHID * 512];
__device__ __half g_W2hiT[NHID * 512];       // W2^T [n][k] (first 256 k used)
__device__ __half g_W2loT[NHID * 512];
__device__ float  g_fs [N_NODES], g_fd [N_NODES];   // layer-1 f-vectors
__device__ float  g_fs2[N_NODES], g_fd2[N_NODES];   // layer-2 f-vectors

// ---------------- packed f32x2 helpers (Blackwell) --------------------------
__device__ __forceinline__ unsigned long long pack_f32x2(float lo, float hi) {
    unsigned long long r;
    asm("mov.b64 %0, {%1, %2};" : "=l"(r) : "f"(lo), "f"(hi));
    return r;
}
__device__ __forceinline__ void unpack_f32x2(float& lo, float& hi, unsigned long long v) {
    asm("mov.b64 {%0, %1}, %2;" : "=f"(lo), "=f"(hi) : "l"(v));
}
#define FMA_F32X2(acc, a, b) \
    asm("fma.rn.f32x2 %0, %1, %2, %0;" : "+l"(acc) : "l"(a), "l"(b))

// ---------------- 0) weight transpose+split, W1 and W2 in ONE launch --------
__global__ __launch_bounds__(256) void conv_weights(const float* __restrict__ W1,
                                                    const float* __restrict__ W2) {
    int b = blockIdx.x;
    const float* W;
    __half *hiT, *loT;
    int i;
    if (b < 512) {
        W = W1; i = b * 256 + threadIdx.x;
        hiT = g_W1hiT; loT = g_W1loT;
    } else {
        W = W2; i = (b - 512) * 256 + threadIdx.x;
        hiT = g_W2hiT; loT = g_W2loT;
    }
    int k = i >> 8, n = i & 255;
    float v = W[i];
    __half h = __float2half_rn(v);
    hiT[n * 512 + k] = h;
    loT[n * 512 + k] = __float2half_rn(v - __half2float(h));
}

// ---------------- 1) adjacency -> ELL: maskless compaction, streaming loads -
__global__ __launch_bounds__(256) void build_ell(const float* __restrict__ adj, int rowOff) {
    const int w    = threadIdx.x >> 5;
    const int lane = threadIdx.x & 31;
    const int row  = rowOff + blockIdx.x * 8 + w;

    const float4* arow = (const float4*)(adj + (size_t)row * N_NODES);  // 2048 float4
    int* crow = g_cols + row * MAXD;

    int cnt = 0;
    #pragma unroll 1
    for (int ch = 0; ch < 8; ch++) {
        const float4* p = arow + ch * 256;
        float4 v[8];
        #pragma unroll
        for (int i = 0; i < 8; i++) v[i] = __ldcs(p + i * 32 + lane);  // streaming

        unsigned mask = 0;
        #pragma unroll
        for (int i = 0; i < 8; i++) {
            mask |= (v[i].x > 0.f ? 1u : 0u) << (i * 4 + 0);
            mask |= (v[i].y > 0.f ? 1u : 0u) << (i * 4 + 1);
            mask |= (v[i].z > 0.f ? 1u : 0u) << (i * 4 + 2);
            mask |= (v[i].w > 0.f ? 1u : 0u) << (i * 4 + 3);
        }
        int c = __popc(mask);
        int incl = c;
        #pragma unroll
        for (int o = 1; o < 32; o <<= 1) {
            int n = __shfl_up_sync(0xffffffffu, incl, o);
            if (lane >= o) incl += n;
        }
        int pos = cnt + incl - c;                 // exclusive prefix
        const int cb = ch * 1024 + lane * 4;      // bit b -> col cb + (b>>2)*128 + (b&3)
        while (mask) {
            int b = __ffs(mask) - 1;
            mask &= mask - 1;
            if (pos < MAXD) crow[pos] = cb + ((b >> 2) << 7) + (b & 3);
            pos++;
        }
        cnt += __shfl_sync(0xffffffffu, incl, 31);  // chunk total
    }
    if (lane == 0) g_deg[row] = (cnt < MAXD) ? cnt : MAXD;
}

// ---------------- 2) tensor-core GEMM (split-fp16, fp32-accurate) -----------
// 64x64 CTA tile (2x the CTAs vs 64x128 -> latency-tolerant under build_ell's
// DRAM contention). 8 warps (2M x 4N), warp tile 32x16 = 2x2 m16n8k16.
// F32A=true: fp32 A split to hi/lo in registers (layer 1).
__device__ __forceinline__ void mma16816(float* c, const unsigned* a, const unsigned* b) {
    asm volatile(
        "mma.sync.aligned.m16n8k16.row.col.f32.f16.f16.f32 "
        "{%0,%1,%2,%3}, {%4,%5,%6,%7}, {%8,%9}, {%0,%1,%2,%3};\n"
        : "+f"(c[0]), "+f"(c[1]), "+f"(c[2]), "+f"(c[3])
        : "r"(a[0]), "r"(a[1]), "r"(a[2]), "r"(a[3]), "r"(b[0]), "r"(b[1]));
}

#define AS_STRIDE 24   // 16 halves + 8 pad: (12g+tg) mod 32 all-distinct banks

template<bool F32A>
__global__ __launch_bounds__(256) void gemm_tc(const float* __restrict__ Af,
                                               const __half* __restrict__ Ahi,
                                               const __half* __restrict__ Alo,
                                               const __half* __restrict__ BhiT,
                                               const __half* __restrict__ BloT,
                                               int K, __half* __restrict__ C, int yOff) {
    __shared__ __half sAhi[2][64 * AS_STRIDE], sAlo[2][64 * AS_STRIDE];
    __shared__ __half sBhi[2][64 * AS_STRIDE], sBlo[2][64 * AS_STRIDE];

    const int tid = threadIdx.x;
    const int wid = tid >> 5, lane = tid & 31;
    const int g = lane >> 2, tg = lane & 3;
    const int warpM = wid >> 2, warpN = wid & 3;    // 2 x 4 warps
    const int rowBase = (blockIdx.y + yOff) * 64;
    const int nBase   = blockIdx.x * 64;

    // loaders: A 64x16 halves = 256 uint2 (1/thread); B 64x16 same
    const int la_r = tid >> 2, la_s = tid & 3;

    const float*  Afp = F32A ? Af + (size_t)(rowBase + la_r) * K + la_s * 4 : nullptr;
    const __half* Ah  = Ahi + (size_t)(rowBase + la_r) * K + la_s * 4;
    const __half* Al  = Alo + (size_t)(rowBase + la_r) * K + la_s * 4;
    const __half* Bh  = BhiT + (size_t)(nBase + la_r) * 512 + la_s * 4;
    const __half* Bl  = BloT + (size_t)(nBase + la_r) * 512 + la_s * 4;

    uint2 rAh, rAl, rBh, rBl;
    auto ldg = [&](int k0) {
        if (F32A) {
            float4 va = *(const float4*)(Afp + k0);
            __half hx = __float2half_rn(va.x), hy = __float2half_rn(va.y);
            __half hz = __float2half_rn(va.z), hw = __float2half_rn(va.w);
            __half2 h01 = __halves2half2(hx, hy), h23 = __halves2half2(hz, hw);
            __half2 l01 = __halves2half2(__float2half_rn(va.x - __half2float(hx)),
                                         __float2half_rn(va.y - __half2float(hy)));
            __half2 l23 = __halves2half2(__float2half_rn(va.z - __half2float(hz)),
                                         __float2half_rn(va.w - __half2float(hw)));
            rAh.x = *(unsigned*)&h01; rAh.y = *(unsigned*)&h23;
            rAl.x = *(unsigned*)&l01; rAl.y = *(unsigned*)&l23;
        } else {
            rAh = *(const uint2*)(Ah + k0);
            rAl = *(const uint2*)(Al + k0);
        }
        rBh = *(const uint2*)(Bh + k0);
        rBl = *(const uint2*)(Bl + k0);
    };
    auto sts = [&](int buf) {
        *(uint2*)&sAhi[buf][la_r * AS_STRIDE + la_s * 4] = rAh;
        *(uint2*)&sAlo[buf][la_r * AS_STRIDE + la_s * 4] = rAl;
        *(uint2*)&sBhi[buf][la_r * AS_STRIDE + la_s * 4] = rBh;
        *(uint2*)&sBlo[buf][la_r * AS_STRIDE + la_s * 4] = rBl;
    };

    float acc[2][2][4] = {};

    ldg(0); sts(0); __syncthreads();
    const int T = K / 16;
    for (int t = 0; t < T; t++) {
        const int buf = t & 1;
        if (t + 1 < T) ldg((t + 1) * 16);

        unsigned ahi[2][4], alo[2][4], bhi[2][2], blo[2][2];
        #pragma unroll
        for (int mt = 0; mt < 2; mt++) {
            int r0 = warpM * 32 + mt * 16 + g;
            ahi[mt][0] = *(const unsigned*)&sAhi[buf][(r0    ) * AS_STRIDE + tg * 2];
            ahi[mt][1] = *(const unsigned*)&sAhi[buf][(r0 + 8) * AS_STRIDE + tg * 2];
            ahi[mt][2] = *(const unsigned*)&sAhi[buf][(r0    ) * AS_STRIDE + tg * 2 + 8];
            ahi[mt][3] = *(const unsigned*)&sAhi[buf][(r0 + 8) * AS_STRIDE + tg * 2 + 8];
            alo[mt][0] = *(const unsigned*)&sAlo[buf][(r0    ) * AS_STRIDE + tg * 2];
            alo[mt][1] = *(const unsigned*)&sAlo[buf][(r0 + 8) * AS_STRIDE + tg * 2];
            alo[mt][2] = *(const unsigned*)&sAlo[buf][(r0    ) * AS_STRIDE + tg * 2 + 8];
            alo[mt][3] = *(const unsigned*)&sAlo[buf][(r0 + 8) * AS_STRIDE + tg * 2 + 8];
        }
        #pragma unroll
        for (int nt = 0; nt < 2; nt++) {
            int n0 = warpN * 16 + nt * 8 + g;
            bhi[nt][0] = *(const unsigned*)&sBhi[buf][n0 * AS_STRIDE + tg * 2];
            bhi[nt][1] = *(const unsigned*)&sBhi[buf][n0 * AS_STRIDE + tg * 2 + 8];
            blo[nt][0] = *(const unsigned*)&sBlo[buf][n0 * AS_STRIDE + tg * 2];
            blo[nt][1] = *(const unsigned*)&sBlo[buf][n0 * AS_STRIDE + tg * 2 + 8];
        }
        #pragma unroll
        for (int mt = 0; mt < 2; mt++)
            #pragma unroll
            for (int nt = 0; nt < 2; nt++) {
                mma16816(acc[mt][nt], ahi[mt], bhi[nt]);
                mma16816(acc[mt][nt], ahi[mt], blo[nt]);
                mma16816(acc[mt][nt], alo[mt], bhi[nt]);
            }
        if (t + 1 < T) sts(buf ^ 1);
        __syncthreads();
    }

    #pragma unroll
    for (int mt = 0; mt < 2; mt++) {
        int r0 = rowBase + warpM * 32 + mt * 16 + g;
        #pragma unroll
        for (int nt = 0; nt < 2; nt++) {
            int c = nBase + warpN * 16 + nt * 8 + tg * 2;
            __half2 h0 = __floats2half2_rn(acc[mt][nt][0], acc[mt][nt][1]);
            __half2 h1 = __floats2half2_rn(acc[mt][nt][2], acc[mt][nt][3]);
            *(__half2*)&C[(size_t)r0 * NHID + c]       = h0;
            *(__half2*)&C[(size_t)(r0 + 8) * NHID + c] = h1;
        }
    }
}

// ---------------- 3) f_src / f_dst: warp-per-row dot(Wh[row], a_half) -------
__global__ __launch_bounds__(256) void fvec_kernel(const __half* __restrict__ Wh,
                                                   const float* __restrict__ a,
                                                   float* __restrict__ fs,
                                                   float* __restrict__ fd, int rowOff) {
    const int w    = threadIdx.x >> 5;
    const int lane = threadIdx.x & 31;
    const int row  = rowOff + blockIdx.x * 8 + w;

    uint4 wv = *(const uint4*)&Wh[(size_t)row * NHID + lane * 8];
    float2 f0 = __half22float2(*(__half2*)&wv.x);
    float2 f1 = __half22float2(*(__half2*)&wv.y);
    float2 f2 = __half22float2(*(__half2*)&wv.z);
    float2 f3 = __half22float2(*(__half2*)&wv.w);

    float4 a0 = *(const float4*)(a + lane * 8);
    float4 a1 = *(const float4*)(a + lane * 8 + 4);
    float4 b0 = *(const float4*)(a + NHID + lane * 8);
    float4 b1 = *(const float4*)(a + NHID + lane * 8 + 4);

    float s1 = f0.x * a0.x + f0.y * a0.y + f1.x * a0.z + f1.y * a0.w
             + f2.x * a1.x + f2.y * a1.y + f3.x * a1.z + f3.y * a1.w;
    float s2 = f0.x * b0.x + f0.y * b0.y + f1.x * b0.z + f1.y * b0.w
             + f2.x * b1.x + f2.y * b1.y + f3.x * b1.z + f3.y * b1.w;
    #pragma unroll
    for (int o = 16; o > 0; o >>= 1) {
        s1 += __shfl_xor_sync(0xffffffffu, s1, o);
        s2 += __shfl_xor_sync(0xffffffffu, s2, o);
    }
    if (lane == 0) { fs[row] = s1; fd[row] = s2; }
}

// ---------------- 4) attn: warp-per-row softmax + SpMM (f32x2) + double ELU -
__global__ __launch_bounds__(256) void attn_kernel(const __half* __restrict__ Wh,
                                                   const float* __restrict__ fs,
                                                   const float* __restrict__ fd,
                                                   float* __restrict__ out,
                                                   int half_out, int rowOff) {
    const int w    = threadIdx.x >> 5;
    const int lane = threadIdx.x & 31;
    const int row  = rowOff + blockIdx.x * 8 + w;

    __shared__ float2 sp[8][MAXD];   // {p_j, byte-offset of Wh row as int bits}

    const int d = g_deg[row];
    const int* crow = g_cols + row * MAXD;
    const float fsr = fs[row];

    float e[8];
    int   c[8];
    #pragma unroll
    for (int i = 0; i < 8; i++) {
        int j = lane + 32 * i;
        if (j < d) {
            c[i] = crow[j];
            float v = fsr + fd[c[i]];
            e[i] = (v > 0.f) ? v : 0.2f * v;    // LeakyReLU(0.2)
        } else {
            e[i] = -3.0e38f;
        }
    }
    float m = e[0];
    #pragma unroll
    for (int i = 1; i < 8; i++) m = fmaxf(m, e[i]);
    #pragma unroll
    for (int o = 16; o > 0; o >>= 1) m = fmaxf(m, __shfl_xor_sync(0xffffffffu, m, o));

    float s = 0.f;
    #pragma unroll
    for (int i = 0; i < 8; i++) {
        int j = lane + 32 * i;
        if (j < d) {
            float pe = expf(e[i] - m);
            s += pe;
            sp[w][j] = make_float2(pe, __int_as_float(c[i] << 9));  // row stride 512 B
        }
    }
    #pragma unroll
    for (int o = 16; o > 0; o >>= 1) s += __shfl_xor_sync(0xffffffffu, s, o);
    const float inv = 1.f / s;
    __syncwarp();

    const char* whbase = (const char*)Wh + lane * 16;
    unsigned long long acc2[4];
    #pragma unroll
    for (int i = 0; i < 4; i++) acc2[i] = pack_f32x2(0.f, 0.f);

    #pragma unroll 8
    for (int j = 0; j < d; j++) {
        float2 po = sp[w][j];
        unsigned long long pj2 = pack_f32x2(po.x, po.x);
        uint4 wv = *(const uint4*)(whbase + __float_as_int(po.y));
        float2 f0 = __half22float2(*(__half2*)&wv.x);
        float2 f1 = __half22float2(*(__half2*)&wv.y);
        float2 f2 = __half22float2(*(__half2*)&wv.z);
        float2 f3 = __half22float2(*(__half2*)&wv.w);
        unsigned long long w0 = pack_f32x2(f0.x, f0.y);
        unsigned long long w1 = pack_f32x2(f1.x, f1.y);
        unsigned long long w2 = pack_f32x2(f2.x, f2.y);
        unsigned long long w3 = pack_f32x2(f3.x, f3.y);
        FMA_F32X2(acc2[0], pj2, w0);
        FMA_F32X2(acc2[1], pj2, w1);
        FMA_F32X2(acc2[2], pj2, w2);
        FMA_F32X2(acc2[3], pj2, w3);
    }

    float acc[8];
    unpack_f32x2(acc[0], acc[1], acc2[0]);
    unpack_f32x2(acc[2], acc[3], acc2[1]);
    unpack_f32x2(acc[4], acc[5], acc2[2]);
    unpack_f32x2(acc[6], acc[7], acc2[3]);

    float h[8];
    #pragma unroll
    for (int i = 0; i < 8; i++) {
        float v = acc[i] * inv;
        float x1 = (v > 0.f) ? v : expm1f(v);
        h[i] = (x1 > 0.f) ? x1 : expm1f(x1);
    }

    if (half_out) {
        __half hi[8], lo[8];
        #pragma unroll
        for (int i = 0; i < 8; i++) {
            hi[i] = __float2half_rn(h[i]);
            lo[i] = __float2half_rn(h[i] - __half2float(hi[i]));
        }
        *(uint4*)&g_Ahi[(size_t)row * NHID + lane * 8] = *(uint4*)hi;
        *(uint4*)&g_Alo[(size_t)row * NHID + lane * 8] = *(uint4*)lo;
    } else {
        float* o = out + (size_t)row * NHID + lane * 8;
        *(float4*)(o + 0) = make_float4(h[0], h[1], h[2], h[3]);
        *(float4*)(o + 4) = make_float4(h[4], h[5], h[6], h[7]);
    }
}

// ---------------- launch ----------------------------------------------------
extern "C" void kernel_launch(void* const* d_in, const int* in_sizes, int n_in,
                              void* d_out, int out_size) {
    const float* x   = (const float*)d_in[0];   // [8192, 512]
    const float* adj = (const float*)d_in[1];   // [8192, 8192]
    const float* W1  = (const float*)d_in[2];   // [512, 256]
    const float* a1  = (const float*)d_in[3];   // [512, 1]
    const float* W2  = (const float*)d_in[4];   // [256, 256]
    const float* a2  = (const float*)d_in[5];   // [512, 1]
    float* out = (float*)d_out;                 // [8192, 256]

    __half *Ahi, *Alo, *W1h, *W1l, *W2h, *W2l, *Whh, *Whh2;
    float *fs, *fd, *fs2, *fd2;
    cudaGetSymbolAddress((void**)&Ahi, g_Ahi);
    cudaGetSymbolAddress((void**)&Alo, g_Alo);
    cudaGetSymbolAddress((void**)&W1h, g_W1hiT);
    cudaGetSymbolAddress((void**)&W1l, g_W1loT);
    cudaGetSymbolAddress((void**)&W2h, g_W2hiT);
    cudaGetSymbolAddress((void**)&W2l, g_W2loT);
    cudaGetSymbolAddress((void**)&Whh, g_Whh);
    cudaGetSymbolAddress((void**)&Whh2, g_Whh2);
    cudaGetSymbolAddress((void**)&fs, g_fs);
    cudaGetSymbolAddress((void**)&fd, g_fd);
    cudaGetSymbolAddress((void**)&fs2, g_fs2);
    cudaGetSymbolAddress((void**)&fd2, g_fd2);

    dim3 gridFull(NHID / 64, N_NODES / 64);     // (4, 128) = 512 CTAs
    dim3 gridHalf(NHID / 64, HALF_N / 64);      // (4, 64)  = 256 CTAs

    // ONE side stream (proven-clean resource profile). sB carries:
    //   build_a -> build_b -> [wait fvec1] -> attn1_b -> gemm2_b -> fvec2_b
    // while main carries conv/gemm1/fvec1 then the half-A pipeline.
    cudaStream_t sB;
    cudaEvent_t evFork, evBA, evPrep, evX;
    cudaStreamCreateWithFlags(&sB, cudaStreamNonBlocking);
    cudaEventCreateWithFlags(&evFork, cudaEventDisableTiming);
    cudaEventCreateWithFlags(&evBA, cudaEventDisableTiming);
    cudaEventCreateWithFlags(&evPrep, cudaEventDisableTiming);
    cudaEventCreateWithFlags(&evX, cudaEventDisableTiming);

    cudaEventRecord(evFork, 0);
    cudaStreamWaitEvent(sB, evFork, 0);
    build_ell<<<HALF_N / 8, 256, 0, sB>>>(adj, 0);
    cudaEventRecord(evBA, sB);
    build_ell<<<HALF_N / 8, 256, 0, sB>>>(adj, HALF_N);

    // main: weights prep + layer-1 GEMM (fp32 x, compile-time split) + fvec1
    conv_weights<<<768, 256>>>(W1, W2);
    gemm_tc<true><<<gridFull, 256>>>(x, Ahi, Alo, W1h, W1l, NFEAT, Whh, 0);
    fvec_kernel<<<N_NODES / 8, 256>>>(Whh, a1, fs, fd, 0);
    cudaEventRecord(evPrep, 0);

    // sB continues: half-B pipeline (after build_b by program order + fvec1)
    cudaStreamWaitEvent(sB, evPrep, 0);
    attn_kernel<<<HALF_N / 8, 256, 0, sB>>>(Whh, fs, fd, nullptr, 1, HALF_N);
    gemm_tc<false><<<gridHalf, 256, 0, sB>>>(nullptr, Ahi, Alo, W2h, W2l, NHID, Whh2, HALF_N / 64);
    fvec_kernel<<<HALF_N / 8, 256, 0, sB>>>(Whh2, a2, fs2, fd2, HALF_N);
    cudaEventRecord(evX, sB);

    // main: half-A pipeline (starts as soon as build_a is done)
    cudaStreamWaitEvent(0, evBA, 0);
    attn_kernel<<<HALF_N / 8, 256>>>(Whh, fs, fd, nullptr, 1, 0);
    gemm_tc<false><<<gridHalf, 256>>>(nullptr, Ahi, Alo, W2h, W2l, NHID, Whh2, 0);
    fvec_kernel<<<HALF_N / 8, 256>>>(Whh2, a2, fs2, fd2, 0);

    // join: attn2 needs full Whh2 + fs2/fd2 + full g_cols
    cudaStreamWaitEvent(0, evX, 0);
    attn_kernel<<<N_NODES / 8, 256>>>(Whh2, fs2, fd2, out, 0, 0);
}